// round 12
// baseline (speedup 1.0000x reference)
#include <cuda_runtime.h>
#include <cuda_fp16.h>
#include <cstdint>

// Problem constants (fixed shapes for GCN_8967891714538)
#define N_NODES 50000
#define N_EDGES 800000
#define IN_CH   128
#define HID_CH  128
#define OUT_CH  64

// ---------------- scratch (static device globals; no allocation) -------------
__device__ __align__(16) __half g_h1[(size_t)N_NODES * HID_CH];   // x @ W1 (fp16)
__device__ __align__(16) __half g_h2[(size_t)N_NODES * OUT_CH];   // a1 @ W2 (fp16)
__device__ __align__(16) __half g_w1h[IN_CH * HID_CH];            // W1^T fp16 [n][k]
__device__ float g_dinv[N_NODES];
__device__ int   g_ecnt[N_NODES];
__device__ int   g_fill[N_NODES];
__device__ int   g_rowptr[N_NODES + 1];
__device__ int   g_esrc[N_EDGES];

// edge_index is int32 (JAX default x64-disabled; R1 OOB crash confirmed 4-byte).

__device__ __forceinline__ float4 half4_to_float4(uint2 u) {
    __half2 h0 = *(__half2*)&u.x;
    __half2 h1 = *(__half2*)&u.y;
    float2 f0 = __half22float2(h0);
    float2 f1 = __half22float2(h1);
    return make_float4(f0.x, f0.y, f1.x, f1.y);
}
__device__ __forceinline__ uint2 float4_to_half4(float a, float b, float c, float d) {
    __half2 h0 = __floats2half2_rn(a, b);
    __half2 h1 = __floats2half2_rn(c, d);
    uint2 u;
    u.x = *(unsigned*)&h0;
    u.y = *(unsigned*)&h1;
    return u;
}

// ---------------- prep: W1 -> fp16 transposed [n][k] ---------------------------
__global__ void k_prepw(const float* __restrict__ W1) {
    int i = blockIdx.x * blockDim.x + threadIdx.x;   // linear over [k][n]
    if (i < IN_CH * HID_CH) {
        int k = i / HID_CH, n = i % HID_CH;
        g_w1h[n * IN_CH + k] = __float2half_rn(W1[i]);
    }
}

// ---------------- CSR build ---------------------------------------------------
__global__ void k_count(const int* __restrict__ ei) {
    int e = blockIdx.x * blockDim.x + threadIdx.x;
    if (e < N_EDGES) {
        int d = ei[N_EDGES + e];
        atomicAdd(&g_ecnt[d], 1);
    }
}

// single-block two-pass scan over 50k degree counts + dinv (replaces
// chunksum+scanfinal; rowptr[N_NODES] == N_EDGES is a compile-time constant)
__global__ void k_scan() {
    __shared__ int ssum[1024];
    const int SEG = (N_NODES + 1023) / 1024;   // 49
    int t  = threadIdx.x;
    int lo = t * SEG;
    int hi = lo + SEG; if (hi > N_NODES) hi = N_NODES;

    int s = 0;
    for (int i = lo; i < hi; i++) s += g_ecnt[i];
    ssum[t] = s;
    __syncthreads();
    for (int off = 1; off < 1024; off <<= 1) {
        int v = (t >= off) ? ssum[t - off] : 0;
        __syncthreads();
        ssum[t] += v;
        __syncthreads();
    }
    int base = ssum[t] - s;   // exclusive prefix of this segment
    for (int i = lo; i < hi; i++) {
        int c = g_ecnt[i];
        g_rowptr[i] = base;
        base += c;
        g_dinv[i] = rsqrtf((float)(c + 1));   // +1 self-loop
    }
    if (t == 0) g_rowptr[N_NODES] = N_EDGES;
}

__global__ void k_fill(const int* __restrict__ ei) {
    int e = blockIdx.x * blockDim.x + threadIdx.x;
    if (e < N_EDGES) {
        int sN = ei[e];
        int d  = ei[N_EDGES + e];
        int pos = g_rowptr[d] + atomicAdd(&g_fill[d], 1);
        g_esrc[pos] = sN;
    }
}

// ---------------- GEMM1: tensor-core mma.sync (fp16 in, fp32 acc, fp16 out) ----
// Block = 128 threads (4 warps), 64 rows x 128 cols. x tile converted fp32->fp16
// into padded smem (stride 136 halves); W1^T fp16 staged to smem. Warp w owns
// rows w*16..w*16+15, all 128 cols (16 n-tiles of 8). Fragment loads are bank-
// conflict-free: bank = 4*(lane/4) + lane%4 covers all 32.
__global__ void __launch_bounds__(128) k_gemm1(const float* __restrict__ X) {
    extern __shared__ __half smem[];
    __half* sx = smem;               // 64 x 136 halves
    __half* sw = smem + 64 * 136;    // 128 x 136 halves

    const int tid  = threadIdx.x;
    const int row0 = blockIdx.x * 64;

    // stage x tile (fp32 -> fp16)
#pragma unroll
    for (int j = 0; j < 16; j++) {
        int idx = j * 128 + tid;     // 2048 float4 slots = 64 rows x 32
        int r   = idx >> 5;
        int k4  = idx & 31;
        float4 v = make_float4(0.f, 0.f, 0.f, 0.f);
        int grow = row0 + r;
        if (grow < N_NODES) v = __ldg((const float4*)(X + (size_t)grow * 128) + k4);
        uint2 u = float4_to_half4(v.x, v.y, v.z, v.w);
        *(uint2*)(sx + r * 136 + k4 * 4) = u;
    }
    // stage W1^T (fp16, already transposed)
#pragma unroll
    for (int j = 0; j < 16; j++) {
        int idx = j * 128 + tid;     // 2048 uint4 slots = 128 rows x 16
        int n   = idx >> 4;
        int kk  = idx & 15;
        uint4 u = *((const uint4*)g_w1h + idx);
        *(uint4*)(sw + n * 136 + kk * 8) = u;
    }
    __syncthreads();

    const int w    = tid >> 5;
    const int lane = tid & 31;
    const int g    = lane >> 2;      // 0..7
    const int tq   = lane & 3;       // 0..3
    const int r0   = w * 16;

    float c[16][4];
#pragma unroll
    for (int t = 0; t < 16; t++)
#pragma unroll
        for (int q = 0; q < 4; q++) c[t][q] = 0.f;

#pragma unroll
    for (int kc = 0; kc < 8; kc++) {
        const int k0 = kc * 16;
        unsigned a0 = *(const unsigned*)(sx + (r0 + g)     * 136 + k0 + tq * 2);
        unsigned a1 = *(const unsigned*)(sx + (r0 + g + 8) * 136 + k0 + tq * 2);
        unsigned a2 = *(const unsigned*)(sx + (r0 + g)     * 136 + k0 + tq * 2 + 8);
        unsigned a3 = *(const unsigned*)(sx + (r0 + g + 8) * 136 + k0 + tq * 2 + 8);
#pragma unroll
        for (int nt = 0; nt < 16; nt++) {
            const int n0 = nt * 8;
            unsigned b0 = *(const unsigned*)(sw + (n0 + g) * 136 + k0 + tq * 2);
            unsigned b1 = *(const unsigned*)(sw + (n0 + g) * 136 + k0 + tq * 2 + 8);
            asm volatile(
                "mma.sync.aligned.m16n8k16.row.col.f32.f16.f16.f32 "
                "{%0,%1,%2,%3}, {%4,%5,%6,%7}, {%8,%9}, {%0,%1,%2,%3};\n"
                : "+f"(c[nt][0]), "+f"(c[nt][1]), "+f"(c[nt][2]), "+f"(c[nt][3])
                : "r"(a0), "r"(a1), "r"(a2), "r"(a3), "r"(b0), "r"(b1));
        }
    }

    // epilogue: fp32 acc -> fp16 h1
    const int gr0 = row0 + r0 + g;
    const int gr1 = gr0 + 8;
#pragma unroll
    for (int nt = 0; nt < 16; nt++) {
        int col = nt * 8 + tq * 2;
        __half2 h01 = __floats2half2_rn(c[nt][0], c[nt][1]);
        __half2 h23 = __floats2half2_rn(c[nt][2], c[nt][3]);
        if (gr0 < N_NODES) *(unsigned*)(g_h1 + (size_t)gr0 * 128 + col) = *(unsigned*)&h01;
        if (gr1 < N_NODES) *(unsigned*)(g_h1 + (size_t)gr1 * 128 + col) = *(unsigned*)&h23;
    }
}

// ---------------- fused agg1 + gemm2 (fp16 h1 in, fp16 h2 out) ------------------
__global__ void __launch_bounds__(256) k_agg1gemm2(const float* __restrict__ b1,
                                                   const float* __restrict__ W2) {
    constexpr int RN = 32;                  // nodes per block
    __shared__ float sa[RN * HID_CH];       // 16 KB a1 tile

    const int tid  = threadIdx.x;
    const int w    = tid >> 5;              // warp 0..7
    const int lane = tid & 31;
    const int nbase = blockIdx.x * RN;

    float4 b;
    {
        const float4* b4 = (const float4*)b1;
        b = __ldg(&b4[lane]);
    }

    // ---- phase 1: aggregate 4 nodes per warp ----
#pragma unroll
    for (int i = 0; i < 4; i++) {
        int node = nbase + w * 4 + i;
        float4 r = make_float4(0.f, 0.f, 0.f, 0.f);
        if (node < N_NODES) {
            float dvn = g_dinv[node];
            const uint2* hrow = (const uint2*)(g_h1 + (size_t)node * HID_CH) + lane;
            float4 self = half4_to_float4(__ldcg(hrow));
            float4 a0, a1v;
            a0.x = self.x * dvn; a0.y = self.y * dvn;
            a0.z = self.z * dvn; a0.w = self.w * dvn;
            a1v = make_float4(0.f, 0.f, 0.f, 0.f);

            const int beg = g_rowptr[node];
            const int end = g_rowptr[node + 1];
            int e = beg;
            for (; e + 2 <= end; e += 2) {
                int s0 = __ldg(&g_esrc[e + 0]);
                int s1 = __ldg(&g_esrc[e + 1]);
                float d0 = __ldcg(&g_dinv[s0]);
                float d1 = __ldcg(&g_dinv[s1]);
                uint2 u0 = __ldcg((const uint2*)(g_h1 + (size_t)s0 * HID_CH) + lane);
                uint2 u1 = __ldcg((const uint2*)(g_h1 + (size_t)s1 * HID_CH) + lane);
                float4 v0 = half4_to_float4(u0);
                float4 v1 = half4_to_float4(u1);
                a0.x = fmaf(v0.x, d0, a0.x); a0.y = fmaf(v0.y, d0, a0.y);
                a0.z = fmaf(v0.z, d0, a0.z); a0.w = fmaf(v0.w, d0, a0.w);
                a1v.x = fmaf(v1.x, d1, a1v.x); a1v.y = fmaf(v1.y, d1, a1v.y);
                a1v.z = fmaf(v1.z, d1, a1v.z); a1v.w = fmaf(v1.w, d1, a1v.w);
            }
            if (e < end) {
                int s0 = __ldg(&g_esrc[e]);
                float d0 = __ldcg(&g_dinv[s0]);
                uint2 u0 = __ldcg((const uint2*)(g_h1 + (size_t)s0 * HID_CH) + lane);
                float4 v0 = half4_to_float4(u0);
                a0.x = fmaf(v0.x, d0, a0.x); a0.y = fmaf(v0.y, d0, a0.y);
                a0.z = fmaf(v0.z, d0, a0.z); a0.w = fmaf(v0.w, d0, a0.w);
            }
            a0.x += a1v.x; a0.y += a1v.y; a0.z += a1v.z; a0.w += a1v.w;

            r.x = fmaxf(fmaf(a0.x, dvn, b.x), 0.f);
            r.y = fmaxf(fmaf(a0.y, dvn, b.y), 0.f);
            r.z = fmaxf(fmaf(a0.z, dvn, b.z), 0.f);
            r.w = fmaxf(fmaf(a0.w, dvn, b.w), 0.f);
        }
        *(float4*)(sa + (w * 4 + i) * HID_CH + lane * 4) = r;
    }
    __syncthreads();

    // ---- phase 2: h2[32 x 64] = sa[32 x 128] @ W2[128 x 64] ----
    constexpr int C   = OUT_CH;     // 64
    constexpr int CT  = C / 4;      // 16 col-threads
    constexpr int RPT = 2;
    const int tx    = tid % CT;
    const int col0  = tx * 4;
    const int rbase = (tid / CT) * RPT;

    float acc[RPT][4];
#pragma unroll
    for (int r = 0; r < RPT; r++)
#pragma unroll
        for (int q = 0; q < 4; q++) acc[r][q] = 0.f;

#pragma unroll 2
    for (int kc = 0; kc < HID_CH / 4; kc++) {
        const int k = kc * 4;
        float4 w0 = __ldg((const float4*)(W2 + (size_t)(k + 0) * C + col0));
        float4 w1 = __ldg((const float4*)(W2 + (size_t)(k + 1) * C + col0));
        float4 w2 = __ldg((const float4*)(W2 + (size_t)(k + 2) * C + col0));
        float4 w3 = __ldg((const float4*)(W2 + (size_t)(k + 3) * C + col0));
#pragma unroll
        for (int r = 0; r < RPT; r++) {
            float4 xv = *(const float4*)(sa + (rbase + r) * HID_CH + k);
            acc[r][0] = fmaf(xv.x, w0.x, acc[r][0]);
            acc[r][1] = fmaf(xv.x, w0.y, acc[r][1]);
            acc[r][2] = fmaf(xv.x, w0.z, acc[r][2]);
            acc[r][3] = fmaf(xv.x, w0.w, acc[r][3]);
            acc[r][0] = fmaf(xv.y, w1.x, acc[r][0]);
            acc[r][1] = fmaf(xv.y, w1.y, acc[r][1]);
            acc[r][2] = fmaf(xv.y, w1.z, acc[r][2]);
            acc[r][3] = fmaf(xv.y, w1.w, acc[r][3]);
            acc[r][0] = fmaf(xv.z, w2.x, acc[r][0]);
            acc[r][1] = fmaf(xv.z, w2.y, acc[r][1]);
            acc[r][2] = fmaf(xv.z, w2.z, acc[r][2]);
            acc[r][3] = fmaf(xv.z, w2.w, acc[r][3]);
            acc[r][0] = fmaf(xv.w, w3.x, acc[r][0]);
            acc[r][1] = fmaf(xv.w, w3.y, acc[r][1]);
            acc[r][2] = fmaf(xv.w, w3.z, acc[r][2]);
            acc[r][3] = fmaf(xv.w, w3.w, acc[r][3]);
        }
    }

#pragma unroll
    for (int r = 0; r < RPT; r++) {
        int row = nbase + rbase + r;
        if (row < N_NODES) {
            uint2 o = float4_to_half4(acc[r][0], acc[r][1], acc[r][2], acc[r][3]);
            *(uint2*)(g_h2 + (size_t)row * C + col0) = o;
        }
    }
}

// ---------------- layer-2 aggregation (fp16 h2 in, fp32 out) --------------------
__global__ void k_agg2(const float* __restrict__ b2, float* __restrict__ out) {
    constexpr int F4 = OUT_CH / 4;   // 16
    int gtid = blockIdx.x * blockDim.x + threadIdx.x;
    int node = gtid / F4;
    int j    = gtid % F4;
    if (node >= N_NODES) return;

    float dvn = g_dinv[node];

    float4 self = half4_to_float4(__ldcg((const uint2*)(g_h2 + (size_t)node * OUT_CH) + j));
    float4 a0, a1;
    a0.x = self.x * dvn; a0.y = self.y * dvn;
    a0.z = self.z * dvn; a0.w = self.w * dvn;
    a1 = make_float4(0.f, 0.f, 0.f, 0.f);

    const int beg = g_rowptr[node];
    const int end = g_rowptr[node + 1];
    int e = beg;
    for (; e + 2 <= end; e += 2) {
        int s0 = __ldg(&g_esrc[e + 0]);
        int s1 = __ldg(&g_esrc[e + 1]);
        float d0 = __ldcg(&g_dinv[s0]);
        float d1 = __ldcg(&g_dinv[s1]);
        float4 v0 = half4_to_float4(__ldcg((const uint2*)(g_h2 + (size_t)s0 * OUT_CH) + j));
        float4 v1 = half4_to_float4(__ldcg((const uint2*)(g_h2 + (size_t)s1 * OUT_CH) + j));
        a0.x = fmaf(v0.x, d0, a0.x); a0.y = fmaf(v0.y, d0, a0.y);
        a0.z = fmaf(v0.z, d0, a0.z); a0.w = fmaf(v0.w, d0, a0.w);
        a1.x = fmaf(v1.x, d1, a1.x); a1.y = fmaf(v1.y, d1, a1.y);
        a1.z = fmaf(v1.z, d1, a1.z); a1.w = fmaf(v1.w, d1, a1.w);
    }
    if (e < end) {
        int s0 = __ldg(&g_esrc[e]);
        float d0 = __ldcg(&g_dinv[s0]);
        float4 v0 = half4_to_float4(__ldcg((const uint2*)(g_h2 + (size_t)s0 * OUT_CH) + j));
        a0.x = fmaf(v0.x, d0, a0.x); a0.y = fmaf(v0.y, d0, a0.y);
        a0.z = fmaf(v0.z, d0, a0.z); a0.w = fmaf(v0.w, d0, a0.w);
    }
    a0.x += a1.x; a0.y += a1.y; a0.z += a1.z; a0.w += a1.w;

    float4 b = __ldg(&((const float4*)b2)[j]);
    float4 r;
    r.x = fmaf(a0.x, dvn, b.x);
    r.y = fmaf(a0.y, dvn, b.y);
    r.z = fmaf(a0.z, dvn, b.z);
    r.w = fmaf(a0.w, dvn, b.w);
    ((float4*)out)[(size_t)node * F4 + j] = r;
}

// ---------------- launch ------------------------------------------------------
// Fork-join: prepw+gemm1 (tensor) on the default stream overlap the CSR build
// (memsets + count + scan + fill) on a side stream; join before fused agg1+gemm2.
// Stream/events created per call and leaked (kernel_launch runs ~2x; timed
// replays execute the captured graph). No device memory allocated.
extern "C" void kernel_launch(void* const* d_in, const int* in_sizes, int n_in,
                              void* d_out, int out_size) {
    const float* x  = (const float*)d_in[0];
    const int*   ei = (const int*)d_in[1];
    const float* W1 = (const float*)d_in[2];
    const float* b1 = (const float*)d_in[3];
    const float* W2 = (const float*)d_in[4];
    const float* b2 = (const float*)d_in[5];
    float* out = (float*)d_out;
    (void)in_sizes; (void)n_in; (void)out_size;

    const int TB = 256;
    const int GEMM1_SMEM = (64 + 128) * 136 * 2;   // 52224 B

    cudaFuncSetAttribute(k_gemm1, cudaFuncAttributeMaxDynamicSharedMemorySize,
                         GEMM1_SMEM);

    void *p_ecnt = nullptr, *p_fill = nullptr;
    cudaGetSymbolAddress(&p_ecnt, g_ecnt);
    cudaGetSymbolAddress(&p_fill, g_fill);

    cudaStream_t s1;
    cudaStreamCreateWithFlags(&s1, cudaStreamNonBlocking);
    cudaEvent_t evA, evB;
    cudaEventCreateWithFlags(&evA, cudaEventDisableTiming);
    cudaEventCreateWithFlags(&evB, cudaEventDisableTiming);

    // fork: side stream joins the (captured) default stream
    cudaEventRecord(evA, 0);
    cudaStreamWaitEvent(s1, evA, 0);

    // default #1: W1 -> fp16 transposed
    k_prepw<<<(IN_CH * HID_CH + TB - 1) / TB, TB>>>(W1);

    // side stream: CSR build
    cudaMemsetAsync(p_ecnt, 0, N_NODES * sizeof(int), s1);
    cudaMemsetAsync(p_fill, 0, N_NODES * sizeof(int), s1);
    k_count<<<(N_EDGES + TB - 1) / TB, TB, 0, s1>>>(ei);   // #2
    k_scan <<<1, 1024, 0, s1>>>();                          // #3

    // default #4 (ncu capture slot): tensor-core Layer-1 GEMM
    k_gemm1<<<(N_NODES + 63) / 64, 128, GEMM1_SMEM>>>(x);

    // side stream: CSR bucket fill                          #5
    k_fill<<<(N_EDGES + TB - 1) / TB, TB, 0, s1>>>(ei);
    cudaEventRecord(evB, s1);

    // join, then fused agg1+gemm2 and final aggregation
    cudaStreamWaitEvent(0, evB, 0);
    k_agg1gemm2<<<(N_NODES + 31) / 32, 256>>>(b1, W2);      // #6
    k_agg2     <<<N_NODES * (OUT_CH / 4) / TB, TB>>>(b2, out); // #7
}

// round 13
// speedup vs baseline: 1.2693x; 1.2693x over previous
#include <cuda_runtime.h>
#include <cuda_fp16.h>
#include <cstdint>

// Problem constants (fixed shapes for GCN_8967891714538)
#define N_NODES 50000
#define N_EDGES 800000
#define IN_CH   128
#define HID_CH  128
#define OUT_CH  64

// ---------------- scratch (static device globals; no allocation) -------------
__device__ __align__(16) __half g_h1[(size_t)N_NODES * HID_CH];   // x @ W1 (fp16)
__device__ __align__(16) __half g_h2[(size_t)N_NODES * OUT_CH];   // a1 @ W2 (fp16)
__device__ __align__(16) __half g_w1h[IN_CH * HID_CH];            // W1^T fp16 [n][k]
__device__ __align__(16) __half g_w2h[OUT_CH * HID_CH];           // W2^T fp16 [n][k]
__device__ float g_dinv[N_NODES];
__device__ int   g_ecnt[N_NODES];
__device__ int   g_fill[N_NODES];
__device__ int   g_rowptr[N_NODES + 1];
__device__ int   g_esrc[N_EDGES];

// edge_index is int32 (JAX default x64-disabled; R1 OOB crash confirmed 4-byte).

__device__ __forceinline__ float4 half4_to_float4(uint2 u) {
    __half2 h0 = *(__half2*)&u.x;
    __half2 h1 = *(__half2*)&u.y;
    float2 f0 = __half22float2(h0);
    float2 f1 = __half22float2(h1);
    return make_float4(f0.x, f0.y, f1.x, f1.y);
}
__device__ __forceinline__ uint2 float4_to_half4(float a, float b, float c, float d) {
    __half2 h0 = __floats2half2_rn(a, b);
    __half2 h1 = __floats2half2_rn(c, d);
    uint2 u;
    u.x = *(unsigned*)&h0;
    u.y = *(unsigned*)&h1;
    return u;
}

// ---------------- prep: W1,W2 -> fp16 transposed [n][k] -------------------------
__global__ void k_prepw(const float* __restrict__ W1, const float* __restrict__ W2) {
    int i = blockIdx.x * blockDim.x + threadIdx.x;
    if (i < IN_CH * HID_CH) {            // W1: [k][n] 128x128
        int k = i / HID_CH, n = i % HID_CH;
        g_w1h[n * IN_CH + k] = __float2half_rn(W1[i]);
    }
    if (i < HID_CH * OUT_CH) {           // W2: [k][n] 128x64
        int k = i / OUT_CH, n = i % OUT_CH;
        g_w2h[n * HID_CH + k] = __float2half_rn(W2[i]);
    }
}

// ---------------- CSR build ---------------------------------------------------
__global__ void k_count(const int* __restrict__ ei) {
    int e = blockIdx.x * blockDim.x + threadIdx.x;
    if (e < N_EDGES) {
        int d = ei[N_EDGES + e];
        atomicAdd(&g_ecnt[d], 1);
    }
}

// single-block two-pass int scan (rowptr only — NO MUFU here; R12 lesson:
// 50k rsqrtf on one SM = ~55us at MUFU rt. dinv is a separate parallel kernel)
__global__ void k_scan() {
    __shared__ int ssum[1024];
    const int SEG = (N_NODES + 1023) / 1024;   // 49
    int t  = threadIdx.x;
    int lo = t * SEG;
    int hi = lo + SEG; if (hi > N_NODES) hi = N_NODES;

    int s = 0;
    for (int i = lo; i < hi; i++) s += g_ecnt[i];
    ssum[t] = s;
    __syncthreads();
    for (int off = 1; off < 1024; off <<= 1) {
        int v = (t >= off) ? ssum[t - off] : 0;
        __syncthreads();
        ssum[t] += v;
        __syncthreads();
    }
    int base = ssum[t] - s;   // exclusive prefix of this segment
    for (int i = lo; i < hi; i++) {
        g_rowptr[i] = base;
        base += g_ecnt[i];
    }
    if (t == 0) g_rowptr[N_NODES] = N_EDGES;
}

__global__ void k_dinv() {
    int v = blockIdx.x * blockDim.x + threadIdx.x;
    if (v < N_NODES) g_dinv[v] = rsqrtf((float)(g_ecnt[v] + 1));  // +1 self-loop
}

__global__ void k_fill(const int* __restrict__ ei) {
    int e = blockIdx.x * blockDim.x + threadIdx.x;
    if (e < N_EDGES) {
        int sN = ei[e];
        int d  = ei[N_EDGES + e];
        int pos = g_rowptr[d] + atomicAdd(&g_fill[d], 1);
        g_esrc[pos] = sN;
    }
}

// ---------------- GEMM1: tensor-core mma.sync (proven in R12) -------------------
__global__ void __launch_bounds__(128) k_gemm1(const float* __restrict__ X) {
    extern __shared__ __half smem[];
    __half* sx = smem;               // 64 x 136 halves
    __half* sw = smem + 64 * 136;    // 128 x 136 halves

    const int tid  = threadIdx.x;
    const int row0 = blockIdx.x * 64;

#pragma unroll
    for (int j = 0; j < 16; j++) {
        int idx = j * 128 + tid;
        int r   = idx >> 5;
        int k4  = idx & 31;
        float4 v = make_float4(0.f, 0.f, 0.f, 0.f);
        int grow = row0 + r;
        if (grow < N_NODES) v = __ldg((const float4*)(X + (size_t)grow * 128) + k4);
        uint2 u = float4_to_half4(v.x, v.y, v.z, v.w);
        *(uint2*)(sx + r * 136 + k4 * 4) = u;
    }
#pragma unroll
    for (int j = 0; j < 16; j++) {
        int idx = j * 128 + tid;
        int n   = idx >> 4;
        int kk  = idx & 15;
        uint4 u = *((const uint4*)g_w1h + idx);
        *(uint4*)(sw + n * 136 + kk * 8) = u;
    }
    __syncthreads();

    const int w    = tid >> 5;
    const int lane = tid & 31;
    const int g    = lane >> 2;
    const int tq   = lane & 3;
    const int r0   = w * 16;

    float c[16][4];
#pragma unroll
    for (int t = 0; t < 16; t++)
#pragma unroll
        for (int q = 0; q < 4; q++) c[t][q] = 0.f;

#pragma unroll
    for (int kc = 0; kc < 8; kc++) {
        const int k0 = kc * 16;
        unsigned a0 = *(const unsigned*)(sx + (r0 + g)     * 136 + k0 + tq * 2);
        unsigned a1 = *(const unsigned*)(sx + (r0 + g + 8) * 136 + k0 + tq * 2);
        unsigned a2 = *(const unsigned*)(sx + (r0 + g)     * 136 + k0 + tq * 2 + 8);
        unsigned a3 = *(const unsigned*)(sx + (r0 + g + 8) * 136 + k0 + tq * 2 + 8);
#pragma unroll
        for (int nt = 0; nt < 16; nt++) {
            const int n0 = nt * 8;
            unsigned b0 = *(const unsigned*)(sw + (n0 + g) * 136 + k0 + tq * 2);
            unsigned b1 = *(const unsigned*)(sw + (n0 + g) * 136 + k0 + tq * 2 + 8);
            asm volatile(
                "mma.sync.aligned.m16n8k16.row.col.f32.f16.f16.f32 "
                "{%0,%1,%2,%3}, {%4,%5,%6,%7}, {%8,%9}, {%0,%1,%2,%3};\n"
                : "+f"(c[nt][0]), "+f"(c[nt][1]), "+f"(c[nt][2]), "+f"(c[nt][3])
                : "r"(a0), "r"(a1), "r"(a2), "r"(a3), "r"(b0), "r"(b1));
        }
    }

    const int gr0 = row0 + r0 + g;
    const int gr1 = gr0 + 8;
#pragma unroll
    for (int nt = 0; nt < 16; nt++) {
        int col = nt * 8 + tq * 2;
        __half2 h01 = __floats2half2_rn(c[nt][0], c[nt][1]);
        __half2 h23 = __floats2half2_rn(c[nt][2], c[nt][3]);
        if (gr0 < N_NODES) *(unsigned*)(g_h1 + (size_t)gr0 * 128 + col) = *(unsigned*)&h01;
        if (gr1 < N_NODES) *(unsigned*)(g_h1 + (size_t)gr1 * 128 + col) = *(unsigned*)&h23;
    }
}

// ---------------- fused agg1 + gemm2 (tensor-core phase 2) ----------------------
// Phase 1: 8 warps x 4 nodes aggregate relu(Â h1 + b1), store fp16 into padded
//          smem tile sa[32 x 136]. Phase 2: h2 = sa @ W2 via m16n8k16 mma
//          (warp w: m-tile w/4, n-tiles (w%4)*16 .. +8), fp16 out.
__global__ void __launch_bounds__(256) k_agg1gemm2(const float* __restrict__ b1) {
    __shared__ __half sa [32 * 136];     // 8.5 KB a1 tile (fp16, padded)
    __shared__ __half sw2[64 * 136];     // 17 KB W2^T tile

    const int tid  = threadIdx.x;
    const int w    = tid >> 5;
    const int lane = tid & 31;
    const int nbase = blockIdx.x * 32;

    // stage W2^T: 64 x 128 halves = 1024 uint4
#pragma unroll
    for (int j = 0; j < 4; j++) {
        int idx = j * 256 + tid;
        int n   = idx >> 4;
        int kk  = idx & 15;
        uint4 u = *((const uint4*)g_w2h + idx);
        *(uint4*)(sw2 + n * 136 + kk * 8) = u;
    }

    float4 b;
    {
        const float4* b4 = (const float4*)b1;
        b = __ldg(&b4[lane]);
    }

    // ---- phase 1: aggregate 4 nodes per warp, write fp16 to sa ----
#pragma unroll
    for (int i = 0; i < 4; i++) {
        int node = nbase + w * 4 + i;
        float4 r = make_float4(0.f, 0.f, 0.f, 0.f);
        if (node < N_NODES) {
            float dvn = g_dinv[node];
            const uint2* hrow = (const uint2*)(g_h1 + (size_t)node * HID_CH) + lane;
            float4 self = half4_to_float4(__ldcg(hrow));
            float4 a0, a1v;
            a0.x = self.x * dvn; a0.y = self.y * dvn;
            a0.z = self.z * dvn; a0.w = self.w * dvn;
            a1v = make_float4(0.f, 0.f, 0.f, 0.f);

            const int beg = g_rowptr[node];
            const int end = g_rowptr[node + 1];
            int e = beg;
            for (; e + 2 <= end; e += 2) {
                int s0 = __ldg(&g_esrc[e + 0]);
                int s1 = __ldg(&g_esrc[e + 1]);
                float d0 = __ldcg(&g_dinv[s0]);
                float d1 = __ldcg(&g_dinv[s1]);
                uint2 u0 = __ldcg((const uint2*)(g_h1 + (size_t)s0 * HID_CH) + lane);
                uint2 u1 = __ldcg((const uint2*)(g_h1 + (size_t)s1 * HID_CH) + lane);
                float4 v0 = half4_to_float4(u0);
                float4 v1 = half4_to_float4(u1);
                a0.x = fmaf(v0.x, d0, a0.x); a0.y = fmaf(v0.y, d0, a0.y);
                a0.z = fmaf(v0.z, d0, a0.z); a0.w = fmaf(v0.w, d0, a0.w);
                a1v.x = fmaf(v1.x, d1, a1v.x); a1v.y = fmaf(v1.y, d1, a1v.y);
                a1v.z = fmaf(v1.z, d1, a1v.z); a1v.w = fmaf(v1.w, d1, a1v.w);
            }
            if (e < end) {
                int s0 = __ldg(&g_esrc[e]);
                float d0 = __ldcg(&g_dinv[s0]);
                uint2 u0 = __ldcg((const uint2*)(g_h1 + (size_t)s0 * HID_CH) + lane);
                float4 v0 = half4_to_float4(u0);
                a0.x = fmaf(v0.x, d0, a0.x); a0.y = fmaf(v0.y, d0, a0.y);
                a0.z = fmaf(v0.z, d0, a0.z); a0.w = fmaf(v0.w, d0, a0.w);
            }
            a0.x += a1v.x; a0.y += a1v.y; a0.z += a1v.z; a0.w += a1v.w;

            r.x = fmaxf(fmaf(a0.x, dvn, b.x), 0.f);
            r.y = fmaxf(fmaf(a0.y, dvn, b.y), 0.f);
            r.z = fmaxf(fmaf(a0.z, dvn, b.z), 0.f);
            r.w = fmaxf(fmaf(a0.w, dvn, b.w), 0.f);
        }
        uint2 u = float4_to_half4(r.x, r.y, r.z, r.w);
        *(uint2*)(sa + (w * 4 + i) * 136 + lane * 4) = u;
    }
    __syncthreads();

    // ---- phase 2: h2[32 x 64] = sa @ W2 via mma ----
    const int g  = lane >> 2;
    const int tq = lane & 3;
    const int m0 = (w >> 2) * 16;          // 0 or 16
    const int nb = (w & 3) * 16;           // 0,16,32,48

    float c[2][4];
#pragma unroll
    for (int t = 0; t < 2; t++)
#pragma unroll
        for (int q = 0; q < 4; q++) c[t][q] = 0.f;

#pragma unroll
    for (int kc = 0; kc < 8; kc++) {
        const int k0 = kc * 16;
        unsigned a0 = *(const unsigned*)(sa + (m0 + g)     * 136 + k0 + tq * 2);
        unsigned a1 = *(const unsigned*)(sa + (m0 + g + 8) * 136 + k0 + tq * 2);
        unsigned a2 = *(const unsigned*)(sa + (m0 + g)     * 136 + k0 + tq * 2 + 8);
        unsigned a3 = *(const unsigned*)(sa + (m0 + g + 8) * 136 + k0 + tq * 2 + 8);
#pragma unroll
        for (int t = 0; t < 2; t++) {
            const int n0 = nb + t * 8;
            unsigned b0 = *(const unsigned*)(sw2 + (n0 + g) * 136 + k0 + tq * 2);
            unsigned b1 = *(const unsigned*)(sw2 + (n0 + g) * 136 + k0 + tq * 2 + 8);
            asm volatile(
                "mma.sync.aligned.m16n8k16.row.col.f32.f16.f16.f32 "
                "{%0,%1,%2,%3}, {%4,%5,%6,%7}, {%8,%9}, {%0,%1,%2,%3};\n"
                : "+f"(c[t][0]), "+f"(c[t][1]), "+f"(c[t][2]), "+f"(c[t][3])
                : "r"(a0), "r"(a1), "r"(a2), "r"(a3), "r"(b0), "r"(b1));
        }
    }

    const int gr0 = nbase + m0 + g;
    const int gr1 = gr0 + 8;
#pragma unroll
    for (int t = 0; t < 2; t++) {
        int col = nb + t * 8 + tq * 2;
        __half2 h01 = __floats2half2_rn(c[t][0], c[t][1]);
        __half2 h23 = __floats2half2_rn(c[t][2], c[t][3]);
        if (gr0 < N_NODES) *(unsigned*)(g_h2 + (size_t)gr0 * OUT_CH + col) = *(unsigned*)&h01;
        if (gr1 < N_NODES) *(unsigned*)(g_h2 + (size_t)gr1 * OUT_CH + col) = *(unsigned*)&h23;
    }
}

// ---------------- layer-2 aggregation (fp16 h2 in, fp32 out) --------------------
__global__ void k_agg2(const float* __restrict__ b2, float* __restrict__ out) {
    constexpr int F4 = OUT_CH / 4;   // 16
    int gtid = blockIdx.x * blockDim.x + threadIdx.x;
    int node = gtid / F4;
    int j    = gtid % F4;
    if (node >= N_NODES) return;

    float dvn = g_dinv[node];

    float4 self = half4_to_float4(__ldcg((const uint2*)(g_h2 + (size_t)node * OUT_CH) + j));
    float4 a0, a1;
    a0.x = self.x * dvn; a0.y = self.y * dvn;
    a0.z = self.z * dvn; a0.w = self.w * dvn;
    a1 = make_float4(0.f, 0.f, 0.f, 0.f);

    const int beg = g_rowptr[node];
    const int end = g_rowptr[node + 1];
    int e = beg;
    for (; e + 2 <= end; e += 2) {
        int s0 = __ldg(&g_esrc[e + 0]);
        int s1 = __ldg(&g_esrc[e + 1]);
        float d0 = __ldcg(&g_dinv[s0]);
        float d1 = __ldcg(&g_dinv[s1]);
        float4 v0 = half4_to_float4(__ldcg((const uint2*)(g_h2 + (size_t)s0 * OUT_CH) + j));
        float4 v1 = half4_to_float4(__ldcg((const uint2*)(g_h2 + (size_t)s1 * OUT_CH) + j));
        a0.x = fmaf(v0.x, d0, a0.x); a0.y = fmaf(v0.y, d0, a0.y);
        a0.z = fmaf(v0.z, d0, a0.z); a0.w = fmaf(v0.w, d0, a0.w);
        a1.x = fmaf(v1.x, d1, a1.x); a1.y = fmaf(v1.y, d1, a1.y);
        a1.z = fmaf(v1.z, d1, a1.z); a1.w = fmaf(v1.w, d1, a1.w);
    }
    if (e < end) {
        int s0 = __ldg(&g_esrc[e]);
        float d0 = __ldcg(&g_dinv[s0]);
        float4 v0 = half4_to_float4(__ldcg((const uint2*)(g_h2 + (size_t)s0 * OUT_CH) + j));
        a0.x = fmaf(v0.x, d0, a0.x); a0.y = fmaf(v0.y, d0, a0.y);
        a0.z = fmaf(v0.z, d0, a0.z); a0.w = fmaf(v0.w, d0, a0.w);
    }
    a0.x += a1.x; a0.y += a1.y; a0.z += a1.z; a0.w += a1.w;

    float4 b = __ldg(&((const float4*)b2)[j]);
    float4 r;
    r.x = fmaf(a0.x, dvn, b.x);
    r.y = fmaf(a0.y, dvn, b.y);
    r.z = fmaf(a0.z, dvn, b.z);
    r.w = fmaf(a0.w, dvn, b.w);
    ((float4*)out)[(size_t)node * F4 + j] = r;
}

// ---------------- launch ------------------------------------------------------
extern "C" void kernel_launch(void* const* d_in, const int* in_sizes, int n_in,
                              void* d_out, int out_size) {
    const float* x  = (const float*)d_in[0];
    const int*   ei = (const int*)d_in[1];
    const float* W1 = (const float*)d_in[2];
    const float* b1 = (const float*)d_in[3];
    const float* W2 = (const float*)d_in[4];
    const float* b2 = (const float*)d_in[5];
    float* out = (float*)d_out;
    (void)in_sizes; (void)n_in; (void)out_size;

    const int TB = 256;
    const int GEMM1_SMEM = (64 + 128) * 136 * 2;   // 52224 B

    cudaFuncSetAttribute(k_gemm1, cudaFuncAttributeMaxDynamicSharedMemorySize,
                         GEMM1_SMEM);

    void *p_ecnt = nullptr, *p_fill = nullptr;
    cudaGetSymbolAddress(&p_ecnt, g_ecnt);
    cudaGetSymbolAddress(&p_fill, g_fill);

    cudaStream_t s1;
    cudaStreamCreateWithFlags(&s1, cudaStreamNonBlocking);
    cudaEvent_t evA, evB;
    cudaEventCreateWithFlags(&evA, cudaEventDisableTiming);
    cudaEventCreateWithFlags(&evB, cudaEventDisableTiming);

    // fork: side stream joins the (captured) default stream
    cudaEventRecord(evA, 0);
    cudaStreamWaitEvent(s1, evA, 0);

    // default: W1/W2 -> fp16 transposed, then tensor-core Layer-1 GEMM
    k_prepw<<<(IN_CH * HID_CH + TB - 1) / TB, TB>>>(W1, W2);

    // side stream: CSR build (memsets -> count -> scan -> dinv -> fill)
    cudaMemsetAsync(p_ecnt, 0, N_NODES * sizeof(int), s1);
    cudaMemsetAsync(p_fill, 0, N_NODES * sizeof(int), s1);
    k_count<<<(N_EDGES + TB - 1) / TB, TB, 0, s1>>>(ei);
    k_scan <<<1, 1024, 0, s1>>>();
    k_dinv <<<(N_NODES + TB - 1) / TB, TB, 0, s1>>>();

    k_gemm1<<<(N_NODES + 63) / 64, 128, GEMM1_SMEM>>>(x);

    k_fill<<<(N_EDGES + TB - 1) / TB, TB, 0, s1>>>(ei);
    cudaEventRecord(evB, s1);

    // join, then fused agg1+gemm2 (tensor) and final aggregation
    cudaStreamWaitEvent(0, evB, 0);
    k_agg1gemm2<<<(N_NODES + 31) / 32, 256>>>(b1);
    k_agg2     <<<N_NODES * (OUT_CH / 4) / TB, TB>>>(b2, out);
}

// round 14
// speedup vs baseline: 1.7813x; 1.4033x over previous
#include <cuda_runtime.h>
#include <cuda_fp16.h>
#include <cstdint>

// Problem constants (fixed shapes for GCN_8967891714538)
#define N_NODES 50000
#define N_EDGES 800000
#define IN_CH   128
#define HID_CH  128
#define OUT_CH  64

#define CHUNK   1024
#define NCHUNKS ((N_NODES + CHUNK - 1) / CHUNK)   // 49

// ---------------- scratch (static device globals; no allocation) -------------
__device__ __align__(16) __half g_h1[(size_t)N_NODES * HID_CH];   // x @ W1 (fp16)
__device__ __align__(16) __half g_h2[(size_t)N_NODES * OUT_CH];   // a1 @ W2 (fp16)
__device__ __align__(16) __half g_w1h[IN_CH * HID_CH];            // W1^T fp16 [n][k]
__device__ __align__(16) __half g_w2h[OUT_CH * HID_CH];           // W2^T fp16 [n][k]
__device__ float g_dinv[N_NODES];
__device__ int   g_cnt[2 * N_NODES];      // [0,N): in-degree  [N,2N): fill cursor
__device__ int   g_rowptr[N_NODES + 1];
__device__ int   g_esrc[N_EDGES];
__device__ int   g_csum[NCHUNKS];

// edge_index is int32 (JAX default x64-disabled; R1 OOB crash confirmed 4-byte).

__device__ __forceinline__ float4 half4_to_float4(uint2 u) {
    __half2 h0 = *(__half2*)&u.x;
    __half2 h1 = *(__half2*)&u.y;
    float2 f0 = __half22float2(h0);
    float2 f1 = __half22float2(h1);
    return make_float4(f0.x, f0.y, f1.x, f1.y);
}
__device__ __forceinline__ uint2 float4_to_half4(float a, float b, float c, float d) {
    __half2 h0 = __floats2half2_rn(a, b);
    __half2 h1 = __floats2half2_rn(c, d);
    uint2 u;
    u.x = *(unsigned*)&h0;
    u.y = *(unsigned*)&h1;
    return u;
}

// ---------------- prep: W1,W2 -> fp16 transposed [n][k] -------------------------
__global__ void k_prepw(const float* __restrict__ W1, const float* __restrict__ W2) {
    int i = blockIdx.x * blockDim.x + threadIdx.x;
    if (i < IN_CH * HID_CH) {            // W1: [k][n] 128x128
        int k = i / HID_CH, n = i % HID_CH;
        g_w1h[n * IN_CH + k] = __float2half_rn(W1[i]);
    }
    if (i < HID_CH * OUT_CH) {           // W2: [k][n] 128x64
        int k = i / OUT_CH, n = i % OUT_CH;
        g_w2h[n * HID_CH + k] = __float2half_rn(W2[i]);
    }
}

// ---------------- CSR build (R11-proven 49-block structure) --------------------
__global__ void k_count(const int* __restrict__ ei) {
    int e = blockIdx.x * blockDim.x + threadIdx.x;
    if (e < N_EDGES) {
        int d = ei[N_EDGES + e];
        atomicAdd(&g_cnt[d], 1);
    }
}

__global__ void k_chunksum() {
    __shared__ int sdata[256];
    int c = blockIdx.x, t = threadIdx.x;
    int base = c * CHUNK;
    int s = 0;
    for (int i = t; i < CHUNK; i += 256) {
        int v = base + i;
        s += (v < N_NODES) ? g_cnt[v] : 0;
    }
    sdata[t] = s;
    __syncthreads();
    for (int off = 128; off > 0; off >>= 1) {
        if (t < off) sdata[t] += sdata[t + off];
        __syncthreads();
    }
    if (t == 0) g_csum[c] = sdata[0];
}

// chunk-local scan + global offset + dinv (49 blocks x 1024; dinv's rsqrtf is
// spread over 49 blocks — NOT one SM, per the R12 MUFU-floor lesson)
__global__ void k_scanfinal() {
    __shared__ int s[CHUNK];
    __shared__ int base;
    int c = blockIdx.x, t = threadIdx.x;
    if (t == 0) {
        int run = 0;
        for (int i = 0; i < c; i++) run += g_csum[i];
        base = run;
    }
    int v = c * CHUNK + t;
    int cnt = (v < N_NODES) ? g_cnt[v] : 0;
    s[t] = cnt;
    __syncthreads();
    for (int off = 1; off < CHUNK; off <<= 1) {
        int val = (t >= off) ? s[t - off] : 0;
        __syncthreads();
        s[t] += val;
        __syncthreads();
    }
    if (v < N_NODES) {
        g_rowptr[v] = base + s[t] - cnt;           // exclusive
        g_dinv[v]   = rsqrtf((float)(cnt + 1));    // +1 self-loop
    }
    if (c == NCHUNKS - 1 && t == 0) {
        g_rowptr[N_NODES] = N_EDGES;
    }
}

__global__ void k_fill(const int* __restrict__ ei) {
    int e = blockIdx.x * blockDim.x + threadIdx.x;
    if (e < N_EDGES) {
        int sN = ei[e];
        int d  = ei[N_EDGES + e];
        int pos = g_rowptr[d] + atomicAdd(&g_cnt[N_NODES + d], 1);
        g_esrc[pos] = sN;
    }
}

// ---------------- GEMM1: tensor-core mma.sync (proven R12: 18.9us) --------------
__global__ void __launch_bounds__(128) k_gemm1(const float* __restrict__ X) {
    extern __shared__ __half smem[];
    __half* sx = smem;               // 64 x 136 halves
    __half* sw = smem + 64 * 136;    // 128 x 136 halves

    const int tid  = threadIdx.x;
    const int row0 = blockIdx.x * 64;

#pragma unroll
    for (int j = 0; j < 16; j++) {
        int idx = j * 128 + tid;
        int r   = idx >> 5;
        int k4  = idx & 31;
        float4 v = make_float4(0.f, 0.f, 0.f, 0.f);
        int grow = row0 + r;
        if (grow < N_NODES) v = __ldg((const float4*)(X + (size_t)grow * 128) + k4);
        uint2 u = float4_to_half4(v.x, v.y, v.z, v.w);
        *(uint2*)(sx + r * 136 + k4 * 4) = u;
    }
#pragma unroll
    for (int j = 0; j < 16; j++) {
        int idx = j * 128 + tid;
        int n   = idx >> 4;
        int kk  = idx & 15;
        uint4 u = *((const uint4*)g_w1h + idx);
        *(uint4*)(sw + n * 136 + kk * 8) = u;
    }
    __syncthreads();

    const int w    = tid >> 5;
    const int lane = tid & 31;
    const int g    = lane >> 2;
    const int tq   = lane & 3;
    const int r0   = w * 16;

    float c[16][4];
#pragma unroll
    for (int t = 0; t < 16; t++)
#pragma unroll
        for (int q = 0; q < 4; q++) c[t][q] = 0.f;

#pragma unroll
    for (int kc = 0; kc < 8; kc++) {
        const int k0 = kc * 16;
        unsigned a0 = *(const unsigned*)(sx + (r0 + g)     * 136 + k0 + tq * 2);
        unsigned a1 = *(const unsigned*)(sx + (r0 + g + 8) * 136 + k0 + tq * 2);
        unsigned a2 = *(const unsigned*)(sx + (r0 + g)     * 136 + k0 + tq * 2 + 8);
        unsigned a3 = *(const unsigned*)(sx + (r0 + g + 8) * 136 + k0 + tq * 2 + 8);
#pragma unroll
        for (int nt = 0; nt < 16; nt++) {
            const int n0 = nt * 8;
            unsigned b0 = *(const unsigned*)(sw + (n0 + g) * 136 + k0 + tq * 2);
            unsigned b1 = *(const unsigned*)(sw + (n0 + g) * 136 + k0 + tq * 2 + 8);
            asm volatile(
                "mma.sync.aligned.m16n8k16.row.col.f32.f16.f16.f32 "
                "{%0,%1,%2,%3}, {%4,%5,%6,%7}, {%8,%9}, {%0,%1,%2,%3};\n"
                : "+f"(c[nt][0]), "+f"(c[nt][1]), "+f"(c[nt][2]), "+f"(c[nt][3])
                : "r"(a0), "r"(a1), "r"(a2), "r"(a3), "r"(b0), "r"(b1));
        }
    }

    const int gr0 = row0 + r0 + g;
    const int gr1 = gr0 + 8;
#pragma unroll
    for (int nt = 0; nt < 16; nt++) {
        int col = nt * 8 + tq * 2;
        __half2 h01 = __floats2half2_rn(c[nt][0], c[nt][1]);
        __half2 h23 = __floats2half2_rn(c[nt][2], c[nt][3]);
        if (gr0 < N_NODES) *(unsigned*)(g_h1 + (size_t)gr0 * 128 + col) = *(unsigned*)&h01;
        if (gr1 < N_NODES) *(unsigned*)(g_h1 + (size_t)gr1 * 128 + col) = *(unsigned*)&h23;
    }
}

// ---------------- fused agg1 + gemm2 (tensor-core phase 2) ----------------------
__global__ void __launch_bounds__(256) k_agg1gemm2(const float* __restrict__ b1) {
    __shared__ __half sa [32 * 136];     // 8.5 KB a1 tile (fp16, padded)
    __shared__ __half sw2[64 * 136];     // 17 KB W2^T tile

    const int tid  = threadIdx.x;
    const int w    = tid >> 5;
    const int lane = tid & 31;
    const int nbase = blockIdx.x * 32;

    // stage W2^T: 64 x 128 halves = 1024 uint4
#pragma unroll
    for (int j = 0; j < 4; j++) {
        int idx = j * 256 + tid;
        int n   = idx >> 4;
        int kk  = idx & 15;
        uint4 u = *((const uint4*)g_w2h + idx);
        *(uint4*)(sw2 + n * 136 + kk * 8) = u;
    }

    float4 b;
    {
        const float4* b4 = (const float4*)b1;
        b = __ldg(&b4[lane]);
    }

    // ---- phase 1: aggregate 4 nodes per warp, write fp16 to sa ----
#pragma unroll
    for (int i = 0; i < 4; i++) {
        int node = nbase + w * 4 + i;
        float4 r = make_float4(0.f, 0.f, 0.f, 0.f);
        if (node < N_NODES) {
            float dvn = g_dinv[node];
            const uint2* hrow = (const uint2*)(g_h1 + (size_t)node * HID_CH) + lane;
            float4 self = half4_to_float4(__ldcg(hrow));
            float4 a0, a1v;
            a0.x = self.x * dvn; a0.y = self.y * dvn;
            a0.z = self.z * dvn; a0.w = self.w * dvn;
            a1v = make_float4(0.f, 0.f, 0.f, 0.f);

            const int beg = g_rowptr[node];
            const int end = g_rowptr[node + 1];
            int e = beg;
            for (; e + 2 <= end; e += 2) {
                int s0 = __ldg(&g_esrc[e + 0]);
                int s1 = __ldg(&g_esrc[e + 1]);
                float d0 = __ldcg(&g_dinv[s0]);
                float d1 = __ldcg(&g_dinv[s1]);
                uint2 u0 = __ldcg((const uint2*)(g_h1 + (size_t)s0 * HID_CH) + lane);
                uint2 u1 = __ldcg((const uint2*)(g_h1 + (size_t)s1 * HID_CH) + lane);
                float4 v0 = half4_to_float4(u0);
                float4 v1 = half4_to_float4(u1);
                a0.x = fmaf(v0.x, d0, a0.x); a0.y = fmaf(v0.y, d0, a0.y);
                a0.z = fmaf(v0.z, d0, a0.z); a0.w = fmaf(v0.w, d0, a0.w);
                a1v.x = fmaf(v1.x, d1, a1v.x); a1v.y = fmaf(v1.y, d1, a1v.y);
                a1v.z = fmaf(v1.z, d1, a1v.z); a1v.w = fmaf(v1.w, d1, a1v.w);
            }
            if (e < end) {
                int s0 = __ldg(&g_esrc[e]);
                float d0 = __ldcg(&g_dinv[s0]);
                uint2 u0 = __ldcg((const uint2*)(g_h1 + (size_t)s0 * HID_CH) + lane);
                float4 v0 = half4_to_float4(u0);
                a0.x = fmaf(v0.x, d0, a0.x); a0.y = fmaf(v0.y, d0, a0.y);
                a0.z = fmaf(v0.z, d0, a0.z); a0.w = fmaf(v0.w, d0, a0.w);
            }
            a0.x += a1v.x; a0.y += a1v.y; a0.z += a1v.z; a0.w += a1v.w;

            r.x = fmaxf(fmaf(a0.x, dvn, b.x), 0.f);
            r.y = fmaxf(fmaf(a0.y, dvn, b.y), 0.f);
            r.z = fmaxf(fmaf(a0.z, dvn, b.z), 0.f);
            r.w = fmaxf(fmaf(a0.w, dvn, b.w), 0.f);
        }
        uint2 u = float4_to_half4(r.x, r.y, r.z, r.w);
        *(uint2*)(sa + (w * 4 + i) * 136 + lane * 4) = u;
    }
    __syncthreads();

    // ---- phase 2: h2[32 x 64] = sa @ W2 via mma ----
    const int g  = lane >> 2;
    const int tq = lane & 3;
    const int m0 = (w >> 2) * 16;          // 0 or 16
    const int nb = (w & 3) * 16;           // 0,16,32,48

    float c[2][4];
#pragma unroll
    for (int t = 0; t < 2; t++)
#pragma unroll
        for (int q = 0; q < 4; q++) c[t][q] = 0.f;

#pragma unroll
    for (int kc = 0; kc < 8; kc++) {
        const int k0 = kc * 16;
        unsigned a0 = *(const unsigned*)(sa + (m0 + g)     * 136 + k0 + tq * 2);
        unsigned a1 = *(const unsigned*)(sa + (m0 + g + 8) * 136 + k0 + tq * 2);
        unsigned a2 = *(const unsigned*)(sa + (m0 + g)     * 136 + k0 + tq * 2 + 8);
        unsigned a3 = *(const unsigned*)(sa + (m0 + g + 8) * 136 + k0 + tq * 2 + 8);
#pragma unroll
        for (int t = 0; t < 2; t++) {
            const int n0 = nb + t * 8;
            unsigned b0 = *(const unsigned*)(sw2 + (n0 + g) * 136 + k0 + tq * 2);
            unsigned b1 = *(const unsigned*)(sw2 + (n0 + g) * 136 + k0 + tq * 2 + 8);
            asm volatile(
                "mma.sync.aligned.m16n8k16.row.col.f32.f16.f16.f32 "
                "{%0,%1,%2,%3}, {%4,%5,%6,%7}, {%8,%9}, {%0,%1,%2,%3};\n"
                : "+f"(c[t][0]), "+f"(c[t][1]), "+f"(c[t][2]), "+f"(c[t][3])
                : "r"(a0), "r"(a1), "r"(a2), "r"(a3), "r"(b0), "r"(b1));
        }
    }

    const int gr0 = nbase + m0 + g;
    const int gr1 = gr0 + 8;
#pragma unroll
    for (int t = 0; t < 2; t++) {
        int col = nb + t * 8 + tq * 2;
        __half2 h01 = __floats2half2_rn(c[t][0], c[t][1]);
        __half2 h23 = __floats2half2_rn(c[t][2], c[t][3]);
        if (gr0 < N_NODES) *(unsigned*)(g_h2 + (size_t)gr0 * OUT_CH + col) = *(unsigned*)&h01;
        if (gr1 < N_NODES) *(unsigned*)(g_h2 + (size_t)gr1 * OUT_CH + col) = *(unsigned*)&h23;
    }
}

// ---------------- layer-2 aggregation (fp16 h2 in, fp32 out) --------------------
__global__ void k_agg2(const float* __restrict__ b2, float* __restrict__ out) {
    constexpr int F4 = OUT_CH / 4;   // 16
    int gtid = blockIdx.x * blockDim.x + threadIdx.x;
    int node = gtid / F4;
    int j    = gtid % F4;
    if (node >= N_NODES) return;

    float dvn = g_dinv[node];

    float4 self = half4_to_float4(__ldcg((const uint2*)(g_h2 + (size_t)node * OUT_CH) + j));
    float4 a0, a1;
    a0.x = self.x * dvn; a0.y = self.y * dvn;
    a0.z = self.z * dvn; a0.w = self.w * dvn;
    a1 = make_float4(0.f, 0.f, 0.f, 0.f);

    const int beg = g_rowptr[node];
    const int end = g_rowptr[node + 1];
    int e = beg;
    for (; e + 2 <= end; e += 2) {
        int s0 = __ldg(&g_esrc[e + 0]);
        int s1 = __ldg(&g_esrc[e + 1]);
        float d0 = __ldcg(&g_dinv[s0]);
        float d1 = __ldcg(&g_dinv[s1]);
        float4 v0 = half4_to_float4(__ldcg((const uint2*)(g_h2 + (size_t)s0 * OUT_CH) + j));
        float4 v1 = half4_to_float4(__ldcg((const uint2*)(g_h2 + (size_t)s1 * OUT_CH) + j));
        a0.x = fmaf(v0.x, d0, a0.x); a0.y = fmaf(v0.y, d0, a0.y);
        a0.z = fmaf(v0.z, d0, a0.z); a0.w = fmaf(v0.w, d0, a0.w);
        a1.x = fmaf(v1.x, d1, a1.x); a1.y = fmaf(v1.y, d1, a1.y);
        a1.z = fmaf(v1.z, d1, a1.z); a1.w = fmaf(v1.w, d1, a1.w);
    }
    if (e < end) {
        int s0 = __ldg(&g_esrc[e]);
        float d0 = __ldcg(&g_dinv[s0]);
        float4 v0 = half4_to_float4(__ldcg((const uint2*)(g_h2 + (size_t)s0 * OUT_CH) + j));
        a0.x = fmaf(v0.x, d0, a0.x); a0.y = fmaf(v0.y, d0, a0.y);
        a0.z = fmaf(v0.z, d0, a0.z); a0.w = fmaf(v0.w, d0, a0.w);
    }
    a0.x += a1.x; a0.y += a1.y; a0.z += a1.z; a0.w += a1.w;

    float4 b = __ldg(&((const float4*)b2)[j]);
    float4 r;
    r.x = fmaf(a0.x, dvn, b.x);
    r.y = fmaf(a0.y, dvn, b.y);
    r.z = fmaf(a0.z, dvn, b.z);
    r.w = fmaf(a0.w, dvn, b.w);
    ((float4*)out)[(size_t)node * F4 + j] = r;
}

// ---------------- launch ------------------------------------------------------
// Fork-join: prepw+gemm1 (tensor) on the default stream overlap the CSR build
// (one memset -> count -> chunksum -> scanfinal(+dinv) -> fill) on a side
// stream; join before fused agg1+gemm2. Stream/events created per call and
// leaked (kernel_launch runs ~2x; replays execute the captured graph).
extern "C" void kernel_launch(void* const* d_in, const int* in_sizes, int n_in,
                              void* d_out, int out_size) {
    const float* x  = (const float*)d_in[0];
    const int*   ei = (const int*)d_in[1];
    const float* W1 = (const float*)d_in[2];
    const float* b1 = (const float*)d_in[3];
    const float* W2 = (const float*)d_in[4];
    const float* b2 = (const float*)d_in[5];
    float* out = (float*)d_out;
    (void)in_sizes; (void)n_in; (void)out_size;

    const int TB = 256;
    const int GEMM1_SMEM = (64 + 128) * 136 * 2;   // 52224 B

    cudaFuncSetAttribute(k_gemm1, cudaFuncAttributeMaxDynamicSharedMemorySize,
                         GEMM1_SMEM);

    void* p_cnt = nullptr;
    cudaGetSymbolAddress(&p_cnt, g_cnt);

    cudaStream_t s1;
    cudaStreamCreateWithFlags(&s1, cudaStreamNonBlocking);
    cudaEvent_t evA, evB;
    cudaEventCreateWithFlags(&evA, cudaEventDisableTiming);
    cudaEventCreateWithFlags(&evB, cudaEventDisableTiming);

    // fork: side stream joins the (captured) default stream
    cudaEventRecord(evA, 0);
    cudaStreamWaitEvent(s1, evA, 0);

    // side stream: CSR build — kernels #1..#4 (fill = capture slot #4)
    cudaMemsetAsync(p_cnt, 0, 2 * N_NODES * sizeof(int), s1);
    k_count    <<<(N_EDGES + TB - 1) / TB, TB, 0, s1>>>(ei);
    k_chunksum <<<NCHUNKS, 256, 0, s1>>>();
    k_scanfinal<<<NCHUNKS, CHUNK, 0, s1>>>();
    k_fill     <<<(N_EDGES + TB - 1) / TB, TB, 0, s1>>>(ei);
    cudaEventRecord(evB, s1);

    // default stream: W prep + tensor-core Layer-1 GEMM (overlaps CSR)
    k_prepw<<<(IN_CH * HID_CH + TB - 1) / TB, TB>>>(W1, W2);
    k_gemm1<<<(N_NODES + 63) / 64, 128, GEMM1_SMEM>>>(x);

    // join, then fused agg1+gemm2 (tensor) and final aggregation
    cudaStreamWaitEvent(0, evB, 0);
    k_agg1gemm2<<<(N_NODES + 31) / 32, 256>>>(b1);
    k_agg2     <<<N_NODES * (OUT_CH / 4) / TB, TB>>>(b2, out);
}